// round 2
// baseline (speedup 1.0000x reference)
#include <cuda_runtime.h>
#include <math.h>

// Problem constants
#define BB 32768
#define TT 7
#define ENC_IN 60
#define DEC_IN 36
#define UU 356
#define G4 (4*UU)      // 1424
#define FDIM (TT*UU)   // 2492
#define HID 768
#define ODIM 168

// ---------------- scratch (device globals; total < 1 GB to keep the host
// shadow symbols within the 2 GB small-code-model range) -----------------
__device__ float g_xz[(size_t)BB * G4];    // per-step input projection [B, 4U]
__device__ float g_zr[(size_t)BB * G4];    // per-step recurrent GEMM   [B, 4U]
__device__ float g_h[(size_t)BB * UU];
__device__ float g_c[(size_t)BB * UU];
__device__ float g_dec[(size_t)BB * FDIM]; // decoder outputs [B, T*U]
__device__ float g_m[(size_t)BB * HID];
__device__ float g_d[(size_t)BB * HID];

// ---------------- generic SGEMM: C[M,N] = act(A[M,K(lda)] @ B[K,N] + bias) --
// Block tile 128x128, K-tile 8, 256 threads, 8x8 per-thread accumulators.
// A row stride = lda (supports strided timestep slices of [B,T,D]).
__global__ __launch_bounds__(256)
void sgemm_kernel(const float* __restrict__ A, const float* __restrict__ B,
                  const float* __restrict__ bias, float* __restrict__ C,
                  int M, int N, int K, int lda, int act)
{
    __shared__ float As[8][128];
    __shared__ float Bs[8][128];

    const int tid = threadIdx.x;
    const int tx = tid & 15;        // N direction (16)
    const int ty = tid >> 4;        // M direction (16)
    const int rowBase = blockIdx.y * 128;
    const int colBase = blockIdx.x * 128;

    float acc[8][8];
#pragma unroll
    for (int i = 0; i < 8; i++)
#pragma unroll
        for (int j = 0; j < 8; j++) acc[i][j] = 0.0f;

    for (int k0 = 0; k0 < K; k0 += 8) {
        // load A tile: 128 rows x 8 k
#pragma unroll
        for (int i = 0; i < 4; i++) {
            int lin = i * 256 + tid;
            int ar = lin >> 3;          // 0..127
            int ak = lin & 7;           // 0..7
            int gr = rowBase + ar;
            int gk = k0 + ak;
            As[ak][ar] = (gr < M && gk < K) ? A[(size_t)gr * lda + gk] : 0.0f;
        }
        // load B tile: 8 k x 128 cols (coalesced)
#pragma unroll
        for (int i = 0; i < 4; i++) {
            int lin = i * 256 + tid;
            int bk = lin >> 7;          // 0..7
            int bc = lin & 127;         // 0..127
            int gk = k0 + bk;
            int gc = colBase + bc;
            Bs[bk][bc] = (gk < K && gc < N) ? B[(size_t)gk * N + gc] : 0.0f;
        }
        __syncthreads();

#pragma unroll
        for (int kk = 0; kk < 8; kk++) {
            float4 a0 = *(const float4*)&As[kk][ty * 8];
            float4 a1 = *(const float4*)&As[kk][ty * 8 + 4];
            float4 b0 = *(const float4*)&Bs[kk][tx * 8];
            float4 b1 = *(const float4*)&Bs[kk][tx * 8 + 4];
            float av[8] = {a0.x, a0.y, a0.z, a0.w, a1.x, a1.y, a1.z, a1.w};
            float bv[8] = {b0.x, b0.y, b0.z, b0.w, b1.x, b1.y, b1.z, b1.w};
#pragma unroll
            for (int i = 0; i < 8; i++)
#pragma unroll
                for (int j = 0; j < 8; j++)
                    acc[i][j] = fmaf(av[i], bv[j], acc[i][j]);
        }
        __syncthreads();
    }

    // epilogue
#pragma unroll
    for (int i = 0; i < 8; i++) {
        int gr = rowBase + ty * 8 + i;
        if (gr >= M) continue;
#pragma unroll
        for (int j = 0; j < 8; j++) {
            int gc = colBase + tx * 8 + j;
            if (gc >= N) continue;
            float v = acc[i][j];
            if (bias) v += bias[gc];
            if (act == 1) v = fmaxf(v, 0.0f);
            else if (act == 2) v = tanhf(v);
            C[(size_t)gr * N + gc] = v;
        }
    }
}

// ---------------- LSTM pointwise gate update -------------------------------
// z = xz[b,:] (+ zrec[b,:] unless first); gates (i,f,g,o)
// c' = sig(f)*c + sig(i)*tanh(g); h' = sig(o)*tanh(c')
__global__ __launch_bounds__(256)
void lstm_cell_kernel(const float* __restrict__ xz,   // [B, 4U]
                      const float* __restrict__ zrec, // [B, 4U] or nullptr
                      float* c_buf,                   // [B, U] in/out
                      float* h_buf,                   // [B, U] out
                      float* __restrict__ seq_out,    // [B, T*U] or nullptr
                      int t, int first)
{
    int idx = blockIdx.x * blockDim.x + threadIdx.x;
    if (idx >= BB * UU) return;
    int b = idx / UU;
    int u = idx - b * UU;

    const float* xr = xz + (size_t)b * G4;
    float zi = xr[u];
    float zf = xr[UU + u];
    float zg = xr[2 * UU + u];
    float zo = xr[3 * UU + u];
    float c;
    if (first) {
        c = 0.0f;
    } else {
        const float* zr = zrec + (size_t)b * G4;
        zi += zr[u];
        zf += zr[UU + u];
        zg += zr[2 * UU + u];
        zo += zr[3 * UU + u];
        c = c_buf[idx];
    }
    float ig = 1.0f / (1.0f + expf(-zi));
    float fg = 1.0f / (1.0f + expf(-zf));
    float gg = tanhf(zg);
    float og = 1.0f / (1.0f + expf(-zo));
    c = fg * c + ig * gg;
    float h = og * tanhf(c);
    c_buf[idx] = c;
    h_buf[idx] = h;
    if (seq_out) seq_out[((size_t)b * TT + t) * UU + u] = h;
}

// ---------------- driver ----------------------------------------------------
static inline dim3 gemm_grid(int M, int N) {
    return dim3((N + 127) / 128, (M + 127) / 128);
}

extern "C" void kernel_launch(void* const* d_in, const int* in_sizes, int n_in,
                              void* d_out, int out_size)
{
    const float* x_batch  = (const float*)d_in[0];
    const float* m_batch  = (const float*)d_in[1];
    const float* enc_k    = (const float*)d_in[2];
    const float* enc_r    = (const float*)d_in[3];
    const float* enc_b    = (const float*)d_in[4];
    const float* dec_k    = (const float*)d_in[5];
    const float* dec_r    = (const float*)d_in[6];
    const float* dec_b    = (const float*)d_in[7];
    const float* W_map    = (const float*)d_in[8];
    const float* b_map    = (const float*)d_in[9];
    const float* W_d1     = (const float*)d_in[10];
    const float* b_d1     = (const float*)d_in[11];
    const float* W_d2     = (const float*)d_in[12];
    const float* b_d2     = (const float*)d_in[13];
    const float* W_out    = (const float*)d_in[14];
    const float* b_out    = (const float*)d_in[15];
    float* out = (float*)d_out;

    float *xz, *zr, *h, *c, *dec, *mbuf, *dbuf;
    cudaGetSymbolAddress((void**)&xz,   g_xz);
    cudaGetSymbolAddress((void**)&zr,   g_zr);
    cudaGetSymbolAddress((void**)&h,    g_h);
    cudaGetSymbolAddress((void**)&c,    g_c);
    cudaGetSymbolAddress((void**)&dec,  g_dec);
    cudaGetSymbolAddress((void**)&mbuf, g_m);
    cudaGetSymbolAddress((void**)&dbuf, g_d);

    const int lstm_blocks = (BB * UU + 255) / 256;
    const dim3 gridBG4 = gemm_grid(BB, G4);

    // ---- encoder ----
    for (int t = 0; t < TT; t++) {
        // xz_t = x[:, t, :] @ enc_k + enc_b   (A is strided slice, lda = T*ENC_IN)
        sgemm_kernel<<<gridBG4, 256>>>(x_batch + (size_t)t * ENC_IN, enc_k, enc_b,
                                       xz, BB, G4, ENC_IN, TT * ENC_IN, 0);
        if (t > 0)
            sgemm_kernel<<<gridBG4, 256>>>(h, enc_r, nullptr, zr, BB, G4, UU, UU, 0);
        lstm_cell_kernel<<<lstm_blocks, 256>>>(xz, (t > 0) ? zr : nullptr,
                                               c, h, nullptr, t, t == 0);
    }

    // ---- decoder (starts from encoder h, c; stores full sequence) ----
    for (int t = 0; t < TT; t++) {
        sgemm_kernel<<<gridBG4, 256>>>(m_batch + (size_t)t * DEC_IN, dec_k, dec_b,
                                       xz, BB, G4, DEC_IN, TT * DEC_IN, 0);
        sgemm_kernel<<<gridBG4, 256>>>(h, dec_r, nullptr, zr, BB, G4, UU, UU, 0);
        lstm_cell_kernel<<<lstm_blocks, 256>>>(xz, zr, c, h, dec, t, 0);
    }

    // ---- MLP head ----
    sgemm_kernel<<<gemm_grid(BB, HID), 256>>>(dec, W_map, b_map, mbuf,
                                              BB, HID, FDIM, FDIM, 1);
    sgemm_kernel<<<gemm_grid(BB, HID), 256>>>(mbuf, W_d1, b_d1, dbuf,
                                              BB, HID, HID, HID, 2);
    sgemm_kernel<<<gemm_grid(BB, HID), 256>>>(dbuf, W_d2, b_d2, mbuf,
                                              BB, HID, HID, HID, 2);
    sgemm_kernel<<<gemm_grid(BB, ODIM), 256>>>(mbuf, W_out, b_out, out,
                                               BB, ODIM, HID, HID, 0);
}

// round 3
// speedup vs baseline: 2.4639x; 2.4639x over previous
#include <cuda_runtime.h>
#include <math.h>
#include <stdint.h>

// Problem constants
#define BB 32768
#define TT 7
#define ENC_IN 60
#define DEC_IN 36
#define UU 356
#define G4 (4*UU)      // 1424
#define FDIM (TT*UU)   // 2492
#define HID 768
#define ODIM 168

// ---------------- scratch (device globals; keep total < ~1 GB) --------------
__device__ float g_xz[(size_t)BB * G4];    // per-step input projection [B, 4U]
__device__ float g_zr[(size_t)BB * G4];    // per-step recurrent GEMM   [B, 4U]
__device__ float g_h[(size_t)BB * UU];
__device__ float g_c[(size_t)BB * UU];
__device__ float g_dec[(size_t)BB * FDIM]; // decoder outputs [B, T*U]
__device__ float g_m[(size_t)BB * HID];
__device__ float g_d[(size_t)BB * HID];

// ---------------- tf32 helpers ----------------------------------------------
__device__ __forceinline__ uint32_t f2tf32(float x) {
    uint32_t r;
    asm("cvt.rna.tf32.f32 %0, %1;" : "=r"(r) : "f"(x));
    return r;
}

__device__ __forceinline__ void mma_tf32(float* c, const uint32_t* a, const uint32_t* b) {
    asm volatile(
        "mma.sync.aligned.m16n8k8.row.col.f32.tf32.tf32.f32 "
        "{%0,%1,%2,%3}, {%4,%5,%6,%7}, {%8,%9}, {%0,%1,%2,%3};"
        : "+f"(c[0]), "+f"(c[1]), "+f"(c[2]), "+f"(c[3])
        : "r"(a[0]), "r"(a[1]), "r"(a[2]), "r"(a[3]), "r"(b[0]), "r"(b[1]));
}

// ---------------- tf32 tensor-core GEMM --------------------------------------
// C[M,N] = act(A[M,K; row stride lda] @ B[K,N] + bias)
// Block tile 128x128, K-tile 32, 256 threads (8 warps, 2x4), warp tile 64x32.
// Requires: K % 4 == 0, N % 4 == 0, 16B-aligned A rows (lda % 4 == 0). All
// shapes in this problem satisfy these.
#define ASTRIDE 36      // 32 + 4 pad (floats)
#define BSTRIDE 132     // 128 + 4 pad (floats)
#define ASIZE (128 * ASTRIDE)   // 4608
#define BSIZE (32 * BSTRIDE)    // 4224
#define SMEM_BYTES ((2 * ASIZE + 2 * BSIZE) * 4)  // 70656

__global__ __launch_bounds__(256)
void tgemm_kernel(const float* __restrict__ A, const float* __restrict__ B,
                  const float* __restrict__ bias, float* __restrict__ C,
                  int M, int N, int K, int lda, int act)
{
    extern __shared__ uint32_t smem[];
    uint32_t* As[2] = { smem, smem + ASIZE };
    uint32_t* Bs[2] = { smem + 2 * ASIZE, smem + 2 * ASIZE + BSIZE };

    const int tid = threadIdx.x;
    const int lane = tid & 31;
    const int warpId = tid >> 5;
    const int wM = (warpId & 1) * 64;
    const int wN = (warpId >> 1) * 32;
    const int g  = lane >> 2;   // group id (0..7)
    const int tg = lane & 3;    // thread-in-group (0..3)
    const int rowBase = blockIdx.y * 128;
    const int colBase = blockIdx.x * 128;

    float acc[4][4][4];
#pragma unroll
    for (int i = 0; i < 4; i++)
#pragma unroll
        for (int j = 0; j < 4; j++)
#pragma unroll
            for (int r = 0; r < 4; r++) acc[i][j][r] = 0.0f;

    const int nTiles = (K + 31) / 32;
    float4 aStage[4], bStage[4];

    // ---- prologue: stage tile 0 ----
    {
        const int k0 = 0;
#pragma unroll
        for (int i = 0; i < 4; i++) {
            int lin = i * 256 + tid;
            int ar = lin >> 3, akq = lin & 7;
            int gr = rowBase + ar, gk = k0 + akq * 4;
            aStage[i] = (gr < M && gk < K) ? *(const float4*)(A + (size_t)gr * lda + gk)
                                           : make_float4(0.f, 0.f, 0.f, 0.f);
        }
#pragma unroll
        for (int i = 0; i < 4; i++) {
            int lin = i * 256 + tid;
            int bk = lin >> 5, bq = lin & 31;
            int gk = k0 + bk, gc = colBase + bq * 4;
            bStage[i] = (gk < K && gc < N) ? *(const float4*)(B + (size_t)gk * N + gc)
                                           : make_float4(0.f, 0.f, 0.f, 0.f);
        }
#pragma unroll
        for (int i = 0; i < 4; i++) {
            int lin = i * 256 + tid;
            int ar = lin >> 3, akq = lin & 7;
            uint4 v = { f2tf32(aStage[i].x), f2tf32(aStage[i].y),
                        f2tf32(aStage[i].z), f2tf32(aStage[i].w) };
            *(uint4*)&As[0][ar * ASTRIDE + akq * 4] = v;
        }
#pragma unroll
        for (int i = 0; i < 4; i++) {
            int lin = i * 256 + tid;
            int bk = lin >> 5, bq = lin & 31;
            uint4 v = { f2tf32(bStage[i].x), f2tf32(bStage[i].y),
                        f2tf32(bStage[i].z), f2tf32(bStage[i].w) };
            *(uint4*)&Bs[0][bk * BSTRIDE + bq * 4] = v;
        }
    }
    __syncthreads();

    for (int t = 0; t < nTiles; t++) {
        const int buf = t & 1;
        const int nxt = buf ^ 1;

        // stage next tile into registers (overlaps with compute)
        if (t + 1 < nTiles) {
            const int k0 = (t + 1) * 32;
#pragma unroll
            for (int i = 0; i < 4; i++) {
                int lin = i * 256 + tid;
                int ar = lin >> 3, akq = lin & 7;
                int gr = rowBase + ar, gk = k0 + akq * 4;
                aStage[i] = (gr < M && gk < K) ? *(const float4*)(A + (size_t)gr * lda + gk)
                                               : make_float4(0.f, 0.f, 0.f, 0.f);
            }
#pragma unroll
            for (int i = 0; i < 4; i++) {
                int lin = i * 256 + tid;
                int bk = lin >> 5, bq = lin & 31;
                int gk = k0 + bk, gc = colBase + bq * 4;
                bStage[i] = (gk < K && gc < N) ? *(const float4*)(B + (size_t)gk * N + gc)
                                               : make_float4(0.f, 0.f, 0.f, 0.f);
            }
        }

        // compute 4 k-steps on current buffer
        const uint32_t* Ab = As[buf];
        const uint32_t* Bb = Bs[buf];
#pragma unroll
        for (int ks = 0; ks < 4; ks++) {
            const int kb = ks * 8;
            uint32_t af[4][4];
#pragma unroll
            for (int mt = 0; mt < 4; mt++) {
                int row = wM + mt * 16;
                af[mt][0] = Ab[(row + g)     * ASTRIDE + kb + tg];
                af[mt][1] = Ab[(row + g + 8) * ASTRIDE + kb + tg];
                af[mt][2] = Ab[(row + g)     * ASTRIDE + kb + tg + 4];
                af[mt][3] = Ab[(row + g + 8) * ASTRIDE + kb + tg + 4];
            }
            uint32_t bf[4][2];
#pragma unroll
            for (int nt = 0; nt < 4; nt++) {
                int col = wN + nt * 8 + g;
                bf[nt][0] = Bb[(kb + tg)     * BSTRIDE + col];
                bf[nt][1] = Bb[(kb + tg + 4) * BSTRIDE + col];
            }
#pragma unroll
            for (int mt = 0; mt < 4; mt++)
#pragma unroll
                for (int nt = 0; nt < 4; nt++)
                    mma_tf32(acc[mt][nt], af[mt], bf[nt]);
        }

        // commit staged tile to the other buffer
        if (t + 1 < nTiles) {
#pragma unroll
            for (int i = 0; i < 4; i++) {
                int lin = i * 256 + tid;
                int ar = lin >> 3, akq = lin & 7;
                uint4 v = { f2tf32(aStage[i].x), f2tf32(aStage[i].y),
                            f2tf32(aStage[i].z), f2tf32(aStage[i].w) };
                *(uint4*)&As[nxt][ar * ASTRIDE + akq * 4] = v;
            }
#pragma unroll
            for (int i = 0; i < 4; i++) {
                int lin = i * 256 + tid;
                int bk = lin >> 5, bq = lin & 31;
                uint4 v = { f2tf32(bStage[i].x), f2tf32(bStage[i].y),
                            f2tf32(bStage[i].z), f2tf32(bStage[i].w) };
                *(uint4*)&Bs[nxt][bk * BSTRIDE + bq * 4] = v;
            }
        }
        __syncthreads();
    }

    // ---- epilogue ----
#pragma unroll
    for (int mt = 0; mt < 4; mt++) {
#pragma unroll
        for (int nt = 0; nt < 4; nt++) {
            int row0 = rowBase + wM + mt * 16 + g;
            int col0 = colBase + wN + nt * 8 + tg * 2;
#pragma unroll
            for (int r = 0; r < 4; r++) {
                int row = row0 + ((r >= 2) ? 8 : 0);
                int col = col0 + (r & 1);
                if (row >= M || col >= N) continue;
                float v = acc[mt][nt][r];
                if (bias) v += bias[col];
                if (act == 1) v = fmaxf(v, 0.0f);
                else if (act == 2) v = tanhf(v);
                C[(size_t)row * N + col] = v;
            }
        }
    }
}

// ---------------- LSTM pointwise gate update -------------------------------
__global__ __launch_bounds__(256)
void lstm_cell_kernel(const float* __restrict__ xz,   // [B, 4U]
                      const float* __restrict__ zrec, // [B, 4U] or nullptr
                      float* c_buf,                   // [B, U] in/out
                      float* h_buf,                   // [B, U] out
                      float* __restrict__ seq_out,    // [B, T*U] or nullptr
                      int t, int first)
{
    int idx = blockIdx.x * blockDim.x + threadIdx.x;
    if (idx >= BB * UU) return;
    int b = idx / UU;
    int u = idx - b * UU;

    const float* xr = xz + (size_t)b * G4;
    float zi = xr[u];
    float zf = xr[UU + u];
    float zg = xr[2 * UU + u];
    float zo = xr[3 * UU + u];
    float c;
    if (first) {
        c = 0.0f;
    } else {
        const float* zr = zrec + (size_t)b * G4;
        zi += zr[u];
        zf += zr[UU + u];
        zg += zr[2 * UU + u];
        zo += zr[3 * UU + u];
        c = c_buf[idx];
    }
    float ig = 1.0f / (1.0f + expf(-zi));
    float fg = 1.0f / (1.0f + expf(-zf));
    float gg = tanhf(zg);
    float og = 1.0f / (1.0f + expf(-zo));
    c = fg * c + ig * gg;
    float h = og * tanhf(c);
    c_buf[idx] = c;
    h_buf[idx] = h;
    if (seq_out) seq_out[((size_t)b * TT + t) * UU + u] = h;
}

// ---------------- driver ----------------------------------------------------
static inline dim3 gemm_grid(int M, int N) {
    return dim3((N + 127) / 128, (M + 127) / 128);
}

extern "C" void kernel_launch(void* const* d_in, const int* in_sizes, int n_in,
                              void* d_out, int out_size)
{
    const float* x_batch  = (const float*)d_in[0];
    const float* m_batch  = (const float*)d_in[1];
    const float* enc_k    = (const float*)d_in[2];
    const float* enc_r    = (const float*)d_in[3];
    const float* enc_b    = (const float*)d_in[4];
    const float* dec_k    = (const float*)d_in[5];
    const float* dec_r    = (const float*)d_in[6];
    const float* dec_b    = (const float*)d_in[7];
    const float* W_map    = (const float*)d_in[8];
    const float* b_map    = (const float*)d_in[9];
    const float* W_d1     = (const float*)d_in[10];
    const float* b_d1     = (const float*)d_in[11];
    const float* W_d2     = (const float*)d_in[12];
    const float* b_d2     = (const float*)d_in[13];
    const float* W_out    = (const float*)d_in[14];
    const float* b_out    = (const float*)d_in[15];
    float* out = (float*)d_out;

    float *xz, *zr, *h, *c, *dec, *mbuf, *dbuf;
    cudaGetSymbolAddress((void**)&xz,   g_xz);
    cudaGetSymbolAddress((void**)&zr,   g_zr);
    cudaGetSymbolAddress((void**)&h,    g_h);
    cudaGetSymbolAddress((void**)&c,    g_c);
    cudaGetSymbolAddress((void**)&dec,  g_dec);
    cudaGetSymbolAddress((void**)&mbuf, g_m);
    cudaGetSymbolAddress((void**)&dbuf, g_d);

    cudaFuncSetAttribute(tgemm_kernel,
                         cudaFuncAttributeMaxDynamicSharedMemorySize, SMEM_BYTES);

    const int lstm_blocks = (BB * UU + 255) / 256;
    const dim3 gridBG4 = gemm_grid(BB, G4);

    // ---- encoder ----
    for (int t = 0; t < TT; t++) {
        tgemm_kernel<<<gridBG4, 256, SMEM_BYTES>>>(
            x_batch + (size_t)t * ENC_IN, enc_k, enc_b, xz,
            BB, G4, ENC_IN, TT * ENC_IN, 0);
        if (t > 0)
            tgemm_kernel<<<gridBG4, 256, SMEM_BYTES>>>(
                h, enc_r, nullptr, zr, BB, G4, UU, UU, 0);
        lstm_cell_kernel<<<lstm_blocks, 256>>>(xz, (t > 0) ? zr : nullptr,
                                               c, h, nullptr, t, t == 0);
    }

    // ---- decoder (starts from encoder h, c; stores full sequence) ----
    for (int t = 0; t < TT; t++) {
        tgemm_kernel<<<gridBG4, 256, SMEM_BYTES>>>(
            m_batch + (size_t)t * DEC_IN, dec_k, dec_b, xz,
            BB, G4, DEC_IN, TT * DEC_IN, 0);
        tgemm_kernel<<<gridBG4, 256, SMEM_BYTES>>>(
            h, dec_r, nullptr, zr, BB, G4, UU, UU, 0);
        lstm_cell_kernel<<<lstm_blocks, 256>>>(xz, zr, c, h, dec, t, 0);
    }

    // ---- MLP head ----
    tgemm_kernel<<<gemm_grid(BB, HID), 256, SMEM_BYTES>>>(
        dec, W_map, b_map, mbuf, BB, HID, FDIM, FDIM, 1);
    tgemm_kernel<<<gemm_grid(BB, HID), 256, SMEM_BYTES>>>(
        mbuf, W_d1, b_d1, dbuf, BB, HID, HID, HID, 2);
    tgemm_kernel<<<gemm_grid(BB, HID), 256, SMEM_BYTES>>>(
        dbuf, W_d2, b_d2, mbuf, BB, HID, HID, HID, 2);
    tgemm_kernel<<<gemm_grid(BB, ODIM), 256, SMEM_BYTES>>>(
        mbuf, W_out, b_out, out, BB, ODIM, HID, HID, 0);
}

// round 5
// speedup vs baseline: 2.7155x; 1.1021x over previous
#include <cuda_runtime.h>
#include <math.h>
#include <stdint.h>

// ---------------- problem constants ----------------
#define BB 32768
#define TT 7
#define ENC_IN 60
#define DEC_IN 36
#define UU 356
#define G4 1424        // 4*UU
#define FDIM 2492      // TT*UU
#define HID 768
#define ODIM 168
#define KP_LSTM 416    // 60+356 (dec 36+356=392, padded to 416)
#define KP_MAP 2496    // padded 2492

// smem: 3 stages x (A 128x36 + B 128x36) floats
#define STG_FLOATS (2 * 128 * 36)          // 9216 floats per stage
#define STG_BYTES  (STG_FLOATS * 4)        // 36864
#define SMEM_BYTES (3 * STG_BYTES)         // 110592

// ---------------- scratch (device globals) ----------------
__device__ float g_wt_enc[(size_t)G4 * KP_LSTM];   // [n=4u+gate][k], tf32 bits
__device__ float g_wt_dec[(size_t)G4 * KP_LSTM];
__device__ float g_bi_enc[G4];
__device__ float g_bi_dec[G4];
__device__ float g_wt_map[(size_t)HID * KP_MAP];
__device__ float g_wt_d1[(size_t)HID * HID];
__device__ float g_wt_d2[(size_t)HID * HID];
__device__ float g_wt_out[(size_t)ODIM * HID];
__device__ float g_xr[(size_t)BB * TT * ENC_IN];   // tf32-rounded x_batch
__device__ float g_mr[(size_t)BB * TT * DEC_IN];   // tf32-rounded m_batch
__device__ float g_h0[(size_t)BB * UU];
__device__ float g_h1[(size_t)BB * UU];
__device__ float g_c[(size_t)BB * UU];
__device__ float g_dec[(size_t)BB * FDIM];
__device__ float g_m[(size_t)BB * HID];
__device__ float g_d[(size_t)BB * HID];

// ---------------- helpers ----------------
__device__ __forceinline__ uint32_t f2tf32(float x) {
    uint32_t r;
    asm("cvt.rna.tf32.f32 %0, %1;" : "=r"(r) : "f"(x));
    return r;
}
__device__ __forceinline__ float tf32r(float x) { return __uint_as_float(f2tf32(x)); }

__device__ __forceinline__ uint32_t smem_u32(const void* p) {
    uint32_t a;
    asm("{ .reg .u64 t; cvta.to.shared.u64 t, %1; cvt.u32.u64 %0, t; }" : "=r"(a) : "l"(p));
    return a;
}
__device__ __forceinline__ void mma_tf32(float* c, const uint32_t* a, const uint32_t* b) {
    asm volatile(
        "mma.sync.aligned.m16n8k8.row.col.f32.tf32.tf32.f32 "
        "{%0,%1,%2,%3}, {%4,%5,%6,%7}, {%8,%9}, {%0,%1,%2,%3};"
        : "+f"(c[0]), "+f"(c[1]), "+f"(c[2]), "+f"(c[3])
        : "r"(a[0]), "r"(a[1]), "r"(a[2]), "r"(a[3]), "r"(b[0]), "r"(b[1]));
}
__device__ __forceinline__ void cpa16(uint32_t dst, const float* src, int sz) {
    asm volatile("cp.async.cg.shared.global [%0], [%1], 16, %2;"
                 :: "r"(dst), "l"(src), "r"(sz) : "memory");
}
#define CPA_COMMIT() asm volatile("cp.async.commit_group;" ::: "memory")
#define CPA_WAIT1()  asm volatile("cp.async.wait_group 1;" ::: "memory")

__device__ __forceinline__ float sigf(float x) { return 1.0f / (1.0f + expf(-x)); }

// ---------------- weight prep (once per launch) ----------------
// Fused LSTM weight: Wt[n=4u+gate][k]: k<KX -> Kx[k][gate*U+u],
// k in [KX,KX+U) -> R[k-KX][gate*U+u], else 0. tf32-rounded.
__global__ void prep_lstm_w(const float* __restrict__ Kx, const float* __restrict__ R,
                            const float* __restrict__ b, float* __restrict__ Wt,
                            float* __restrict__ biasI, int KX)
{
    int idx = blockIdx.x * blockDim.x + threadIdx.x;
    if (idx >= G4 * KP_LSTM) return;
    int n = idx / KP_LSTM, k = idx - n * KP_LSTM;
    int u = n >> 2, gate = n & 3;
    int colw = gate * UU + u;
    float v = 0.0f;
    if (k < KX) v = Kx[(size_t)k * G4 + colw];
    else if (k < KX + UU) v = R[(size_t)(k - KX) * G4 + colw];
    Wt[idx] = tf32r(v);
    if (k == 0) biasI[n] = b[colw];
}

// transpose + tf32: W[K,N] -> Wt[N,Kpad]
__global__ void prep_trans(const float* __restrict__ W, float* __restrict__ Wt,
                           int K, int N, int Kpad)
{
    int idx = blockIdx.x * blockDim.x + threadIdx.x;
    if (idx >= N * Kpad) return;
    int n = idx / Kpad, k = idx - n * Kpad;
    Wt[idx] = (k < K) ? tf32r(W[(size_t)k * N + n]) : 0.0f;
}

__global__ void round_copy(const float* __restrict__ src, float* __restrict__ dst, int n)
{
    int i = blockIdx.x * blockDim.x + threadIdx.x;
    if (i < n) dst[i] = tf32r(src[i]);
}

// ---------------- tf32 mma.sync GEMM, cp.async 3-stage, fused epilogues -----
// D = A[M,Kpad] @ Bt[N,Kpad]^T;  A = concat(A1[:,0:K1], A2[:,0:UU], 0-pad)
// act: 0 bias, 1 bias+relu(+tf32 round), 2 bias+tanh(+round), 3 LSTM cell
__global__ __launch_bounds__(256)
void mm_gemm(const float* __restrict__ A1, int lda1, int K1,
             const float* __restrict__ A2,
             const float* __restrict__ Bt, int ldb,
             const float* __restrict__ bias,
             float* __restrict__ C, int ldc,
             int N, int Kpad, int act,
             float* __restrict__ c_state, float* __restrict__ h_out,
             float* __restrict__ seq_out, int t, int first)
{
    extern __shared__ float smem[];
    const uint32_t sbase = smem_u32(smem);
    const int tid = threadIdx.x;
    const int wid = tid >> 5, lane = tid & 31;
    const int g = lane >> 2, tg = lane & 3;
    const int wM = (wid & 1) * 64, wN = (wid >> 1) * 32;
    const int rowBase = blockIdx.y * 128, colBase = blockIdx.x * 128;
    const int nT = Kpad >> 5;

    // per-thread async-copy coordinates: half-row (64B) per thread per tile
    const int arow = tid >> 1;         // 0..127
    const int hseg = tid & 1;          // 0,1 -> k offset 16 floats
    const int grow = rowBase + arow;   // A global row (M divisible by 128)
    const int gn = colBase + arow;     // B global row (n)
    const float* bRow = Bt + (size_t)gn * ldb;
    const int bsz = (gn < N) ? 16 : 0;
    const uint32_t dstA = sbase + (uint32_t)(arow * 144 + hseg * 64);
    const uint32_t dstB = dstA + 18432u;

    auto issue = [&](int kt, int slot) {
        const int k0 = kt * 32 + hseg * 16;
        const uint32_t so = (uint32_t)slot * STG_BYTES;
#pragma unroll
        for (int j = 0; j < 4; j++) {
            int kg = k0 + j * 4;
            const float* p;
            int sz = 16;
            if (kg < K1) p = A1 + (size_t)grow * lda1 + kg;
            else if (A2 != nullptr && kg < K1 + UU) p = A2 + (size_t)grow * UU + (kg - K1);
            else { p = A1; sz = 0; }
            cpa16(dstA + so + j * 16, p, sz);
        }
#pragma unroll
        for (int j = 0; j < 4; j++)
            cpa16(dstB + so + j * 16, bRow + k0 + j * 4, bsz);
        CPA_COMMIT();
    };

    float acc[4][4][4];
#pragma unroll
    for (int i = 0; i < 4; i++)
#pragma unroll
        for (int j = 0; j < 4; j++)
#pragma unroll
            for (int r = 0; r < 4; r++) acc[i][j][r] = 0.0f;

    // prologue: 2 tiles in flight
    issue(0, 0);
    if (nT > 1) issue(1, 1); else CPA_COMMIT();

    for (int kt = 0; kt < nT; kt++) {
        CPA_WAIT1();
        __syncthreads();
        if (kt + 2 < nT) issue(kt + 2, (kt + 2) % 3);

        const float* As = smem + (kt % 3) * STG_FLOATS;
        const float* Bs = As + 4608;
#pragma unroll
        for (int ks = 0; ks < 4; ks++) {
            const int kb = ks * 8;
            uint32_t af[4][4];
#pragma unroll
            for (int mt = 0; mt < 4; mt++) {
                const float* pa = As + (wM + mt * 16 + g) * 36 + kb + tg;
                af[mt][0] = __float_as_uint(pa[0]);
                af[mt][1] = __float_as_uint(pa[8 * 36]);
                af[mt][2] = __float_as_uint(pa[4]);
                af[mt][3] = __float_as_uint(pa[8 * 36 + 4]);
            }
            uint32_t bf[4][2];
#pragma unroll
            for (int nt = 0; nt < 4; nt++) {
                const float* pb = Bs + (wN + nt * 8 + g) * 36 + kb + tg;
                bf[nt][0] = __float_as_uint(pb[0]);
                bf[nt][1] = __float_as_uint(pb[4]);
            }
#pragma unroll
            for (int mt = 0; mt < 4; mt++)
#pragma unroll
                for (int nt = 0; nt < 4; nt++)
                    mma_tf32(acc[mt][nt], af[mt], bf[nt]);
        }
    }
    __syncthreads();

    // ---- epilogues ----
    if (act == 3) {
        // LSTM cell: cols are gate quads (i,f,g,o) per unit u = col/4.
        // Lane pair (tg even, tg odd) holds one quad: even lane has cols 4u,4u+1
        // (i,f), odd lane has 4u+2,4u+3 (g,o). Gather odd lane's regs via shfl.
#pragma unroll
        for (int mt = 0; mt < 4; mt++) {
#pragma unroll
            for (int nt = 0; nt < 4; nt++) {
                float c0 = acc[mt][nt][0], c1 = acc[mt][nt][1];
                float c2 = acc[mt][nt][2], c3 = acc[mt][nt][3];
                float d0 = __shfl_xor_sync(0xFFFFFFFFu, c0, 1);
                float d1 = __shfl_xor_sync(0xFFFFFFFFu, c1, 1);
                float d2 = __shfl_xor_sync(0xFFFFFFFFu, c2, 1);
                float d3 = __shfl_xor_sync(0xFFFFFFFFu, c3, 1);
                if ((tg & 1) == 0) {
                    int quad = colBase + wN + nt * 8 + tg * 2;
                    if (quad < N) {
                        int u = quad >> 2;
                        float b0 = bias[quad], b1 = bias[quad + 1];
                        float b2 = bias[quad + 2], b3 = bias[quad + 3];
                        int row0 = rowBase + wM + mt * 16 + g;
#pragma unroll
                        for (int rr = 0; rr < 2; rr++) {
                            int row = row0 + rr * 8;
                            float zi = (rr ? c2 : c0) + b0;
                            float zf = (rr ? c3 : c1) + b1;
                            float zg = (rr ? d2 : d0) + b2;
                            float zo = (rr ? d3 : d1) + b3;
                            size_t si = (size_t)row * UU + u;
                            float cp = first ? 0.0f : c_state[si];
                            float cn = sigf(zf) * cp + sigf(zi) * tanhf(zg);
                            float hh = sigf(zo) * tanhf(cn);
                            c_state[si] = cn;
                            float hr = tf32r(hh);
                            h_out[si] = hr;
                            if (seq_out)
                                seq_out[(size_t)row * FDIM + t * UU + u] = hr;
                        }
                    }
                }
            }
        }
    } else {
#pragma unroll
        for (int mt = 0; mt < 4; mt++) {
#pragma unroll
            for (int nt = 0; nt < 4; nt++) {
                int col = colBase + wN + nt * 8 + tg * 2;
                if (col >= N) continue;
                float b0 = bias[col], b1 = bias[col + 1];
                int row0 = rowBase + wM + mt * 16 + g;
#pragma unroll
                for (int rr = 0; rr < 2; rr++) {
                    int row = row0 + rr * 8;
                    float v0 = acc[mt][nt][rr * 2]     + b0;
                    float v1 = acc[mt][nt][rr * 2 + 1] + b1;
                    if (act == 1) {
                        v0 = tf32r(fmaxf(v0, 0.0f)); v1 = tf32r(fmaxf(v1, 0.0f));
                    } else if (act == 2) {
                        v0 = tf32r(tanhf(v0)); v1 = tf32r(tanhf(v1));
                    }
                    *(float2*)(C + (size_t)row * ldc + col) = make_float2(v0, v1);
                }
            }
        }
    }
}

// ---------------- driver ----------------
extern "C" void kernel_launch(void* const* d_in, const int* in_sizes, int n_in,
                              void* d_out, int out_size)
{
    const float* x_batch = (const float*)d_in[0];
    const float* m_batch = (const float*)d_in[1];
    const float* enc_k   = (const float*)d_in[2];
    const float* enc_r   = (const float*)d_in[3];
    const float* enc_b   = (const float*)d_in[4];
    const float* dec_k   = (const float*)d_in[5];
    const float* dec_r   = (const float*)d_in[6];
    const float* dec_b   = (const float*)d_in[7];
    const float* W_map   = (const float*)d_in[8];
    const float* b_map   = (const float*)d_in[9];
    const float* W_d1    = (const float*)d_in[10];
    const float* b_d1    = (const float*)d_in[11];
    const float* W_d2    = (const float*)d_in[12];
    const float* b_d2    = (const float*)d_in[13];
    const float* W_out   = (const float*)d_in[14];
    const float* b_out   = (const float*)d_in[15];
    float* out = (float*)d_out;

    float *wt_enc, *wt_dec, *bi_enc, *bi_dec, *wt_map, *wt_d1, *wt_d2, *wt_out;
    float *xr, *mr, *h0, *h1, *c, *dec, *mbuf, *dbuf;
    cudaGetSymbolAddress((void**)&wt_enc, g_wt_enc);
    cudaGetSymbolAddress((void**)&wt_dec, g_wt_dec);
    cudaGetSymbolAddress((void**)&bi_enc, g_bi_enc);
    cudaGetSymbolAddress((void**)&bi_dec, g_bi_dec);
    cudaGetSymbolAddress((void**)&wt_map, g_wt_map);
    cudaGetSymbolAddress((void**)&wt_d1,  g_wt_d1);
    cudaGetSymbolAddress((void**)&wt_d2,  g_wt_d2);
    cudaGetSymbolAddress((void**)&wt_out, g_wt_out);
    cudaGetSymbolAddress((void**)&xr,     g_xr);
    cudaGetSymbolAddress((void**)&mr,     g_mr);
    cudaGetSymbolAddress((void**)&h0,     g_h0);
    cudaGetSymbolAddress((void**)&h1,     g_h1);
    cudaGetSymbolAddress((void**)&c,      g_c);
    cudaGetSymbolAddress((void**)&dec,    g_dec);
    cudaGetSymbolAddress((void**)&mbuf,   g_m);
    cudaGetSymbolAddress((void**)&dbuf,   g_d);

    cudaFuncSetAttribute(mm_gemm, cudaFuncAttributeMaxDynamicSharedMemorySize, SMEM_BYTES);

    // ---- prep: tf32-round weights + inputs (once per replay) ----
    {
        int n1 = G4 * KP_LSTM;
        prep_lstm_w<<<(n1 + 255) / 256, 256>>>(enc_k, enc_r, enc_b, wt_enc, bi_enc, ENC_IN);
        prep_lstm_w<<<(n1 + 255) / 256, 256>>>(dec_k, dec_r, dec_b, wt_dec, bi_dec, DEC_IN);
        int n2 = HID * KP_MAP;
        prep_trans<<<(n2 + 255) / 256, 256>>>(W_map, wt_map, FDIM, HID, KP_MAP);
        int n3 = HID * HID;
        prep_trans<<<(n3 + 255) / 256, 256>>>(W_d1, wt_d1, HID, HID, HID);
        prep_trans<<<(n3 + 255) / 256, 256>>>(W_d2, wt_d2, HID, HID, HID);
        int n4 = ODIM * HID;
        prep_trans<<<(n4 + 255) / 256, 256>>>(W_out, wt_out, HID, ODIM, HID);
        int nx = BB * TT * ENC_IN;
        round_copy<<<(nx + 255) / 256, 256>>>(x_batch, xr, nx);
        int nm = BB * TT * DEC_IN;
        round_copy<<<(nm + 255) / 256, 256>>>(m_batch, mr, nm);
    }

    const dim3 gridLSTM((G4 + 127) / 128, BB / 128);   // 12 x 256
    const dim3 gridHID(HID / 128, BB / 128);           // 6 x 256
    const dim3 gridOUT((ODIM + 127) / 128, BB / 128);  // 2 x 256

    float* hin = h0;
    float* hout = h1;

    // ---- encoder (fused input-proj + recurrent + cell) ----
    // t=0: h=c=0 -> K = 60 padded to 64, no A2
    mm_gemm<<<gridLSTM, 256, SMEM_BYTES>>>(
        xr, TT * ENC_IN, ENC_IN, nullptr, wt_enc, KP_LSTM, bi_enc,
        nullptr, 0, G4, 64, 3, c, hout, nullptr, 0, 1);
    { float* tmp = hin; hin = hout; hout = tmp; }
    for (int t = 1; t < TT; t++) {
        mm_gemm<<<gridLSTM, 256, SMEM_BYTES>>>(
            xr + (size_t)t * ENC_IN, TT * ENC_IN, ENC_IN, hin, wt_enc, KP_LSTM,
            bi_enc, nullptr, 0, G4, KP_LSTM, 3, c, hout, nullptr, t, 0);
        float* tmp = hin; hin = hout; hout = tmp;
    }

    // ---- decoder (stores sequence into g_dec) ----
    for (int t = 0; t < TT; t++) {
        mm_gemm<<<gridLSTM, 256, SMEM_BYTES>>>(
            mr + (size_t)t * DEC_IN, TT * DEC_IN, DEC_IN, hin, wt_dec, KP_LSTM,
            bi_dec, nullptr, 0, G4, KP_LSTM, 3, c, hout, dec, t, 0);
        float* tmp = hin; hin = hout; hout = tmp;
    }

    // ---- MLP head ----
    mm_gemm<<<gridHID, 256, SMEM_BYTES>>>(
        dec, FDIM, FDIM, nullptr, wt_map, KP_MAP, b_map,
        mbuf, HID, HID, KP_MAP, 1, nullptr, nullptr, nullptr, 0, 0);
    mm_gemm<<<gridHID, 256, SMEM_BYTES>>>(
        mbuf, HID, HID, nullptr, wt_d1, HID, b_d1,
        dbuf, HID, HID, HID, 2, nullptr, nullptr, nullptr, 0, 0);
    mm_gemm<<<gridHID, 256, SMEM_BYTES>>>(
        dbuf, HID, HID, nullptr, wt_d2, HID, b_d2,
        mbuf, HID, HID, HID, 2, nullptr, nullptr, nullptr, 0, 0);
    mm_gemm<<<gridOUT, 256, SMEM_BYTES>>>(
        mbuf, HID, HID, nullptr, wt_out, HID, b_out,
        out, ODIM, ODIM, HID, 0, nullptr, nullptr, nullptr, 0, 0);
}

// round 6
// speedup vs baseline: 3.7893x; 1.3954x over previous
#include <cuda_runtime.h>
#include <cuda_fp16.h>
#include <math.h>
#include <stdint.h>

// ---------------- problem constants ----------------
#define BB 32768
#define TT 7
#define ENC_IN 60
#define DEC_IN 36
#define UU 356
#define G4 1424        // 4*UU
#define FDIM 2492      // TT*UU
#define FDIMP 2496     // padded (16B-aligned half rows)
#define HID 768
#define ODIM 168
#define HS 360         // padded h stride (halfs, 720B rows)
#define KE1 64         // enc x slice padded (60->64)
#define KD1 40         // dec m slice padded (36->40)
#define KP_LSTM 448    // 64+360 = 424 -> 448 (7 k-tiles of 64)

// smem: 3 stages x (A 128 rows x 144B + B 128 x 144B)
#define STG_BYTES  36864
#define STG_HALFS  (STG_BYTES / 2)
#define SMEM_BYTES (3 * STG_BYTES)         // 110592

// ---------------- scratch (device globals) ----------------
__device__ __half g_wt_enc[(size_t)G4 * KP_LSTM];   // [n=4u+gate][k]
__device__ __half g_wt_dec[(size_t)G4 * KP_LSTM];
__device__ float  g_bi_enc[G4];
__device__ float  g_bi_dec[G4];
__device__ __half g_wt_map[(size_t)HID * FDIMP];
__device__ __half g_wt_d1[(size_t)HID * HID];
__device__ __half g_wt_d2[(size_t)HID * HID];
__device__ __half g_wt_out[(size_t)ODIM * HID];
__device__ __half g_xr[(size_t)BB * TT * KE1];      // [B][T*64]
__device__ __half g_mr[(size_t)BB * TT * KD1];      // [B][T*40]
__device__ __half g_h0[(size_t)BB * HS];
__device__ __half g_h1[(size_t)BB * HS];
__device__ float  g_c[(size_t)BB * UU];
__device__ __half g_dec[(size_t)BB * FDIMP];
__device__ __half g_m[(size_t)BB * HID];
__device__ __half g_d[(size_t)BB * HID];

// ---------------- helpers ----------------
__device__ __forceinline__ uint32_t smem_u32(const void* p) {
    uint32_t a;
    asm("{ .reg .u64 t; cvta.to.shared.u64 t, %1; cvt.u32.u64 %0, t; }" : "=r"(a) : "l"(p));
    return a;
}
__device__ __forceinline__ void mma_f16(float* c, const uint32_t* a, const uint32_t* b) {
    asm volatile(
        "mma.sync.aligned.m16n8k16.row.col.f32.f16.f16.f32 "
        "{%0,%1,%2,%3}, {%4,%5,%6,%7}, {%8,%9}, {%0,%1,%2,%3};"
        : "+f"(c[0]), "+f"(c[1]), "+f"(c[2]), "+f"(c[3])
        : "r"(a[0]), "r"(a[1]), "r"(a[2]), "r"(a[3]), "r"(b[0]), "r"(b[1]));
}
__device__ __forceinline__ void cpa16(uint32_t dst, const void* src, int sz) {
    asm volatile("cp.async.cg.shared.global [%0], [%1], 16, %2;"
                 :: "r"(dst), "l"(src), "r"(sz) : "memory");
}
#define CPA_COMMIT() asm volatile("cp.async.commit_group;" ::: "memory")
#define CPA_WAIT1()  asm volatile("cp.async.wait_group 1;" ::: "memory")

__device__ __forceinline__ float sigf(float x) { return 1.0f / (1.0f + expf(-x)); }

// ---------------- prep kernels (run every launch; ~tens of us) --------------
// LSTM fused weight, gate-interleaved: Wt[n=4u+gate][k];
// k<KX -> Kx[k][gate*U+u]; K1<=k<K1+U -> R[k-K1][gate*U+u]; else 0.
__global__ void prep_lstm_w(const float* __restrict__ Kx, const float* __restrict__ R,
                            const float* __restrict__ b, __half* __restrict__ Wt,
                            float* __restrict__ biasI, int KX, int K1)
{
    int idx = blockIdx.x * blockDim.x + threadIdx.x;
    if (idx >= G4 * KP_LSTM) return;
    int n = idx / KP_LSTM, k = idx - n * KP_LSTM;
    int u = n >> 2, gate = n & 3;
    int colw = gate * UU + u;
    float v = 0.0f;
    if (k < KX) v = Kx[(size_t)k * G4 + colw];
    else if (k >= K1 && k < K1 + UU) v = R[(size_t)(k - K1) * G4 + colw];
    Wt[idx] = __float2half(v);
    if (k == 0) biasI[n] = b[colw];
}

// transpose: W[K,N] float -> Wt[N,Kpad] half
__global__ void prep_trans(const float* __restrict__ W, __half* __restrict__ Wt,
                           int K, int N, int Kpad)
{
    int idx = blockIdx.x * blockDim.x + threadIdx.x;
    if (idx >= N * Kpad) return;
    int n = idx / Kpad, k = idx - n * Kpad;
    Wt[idx] = __float2half((k < K) ? W[(size_t)k * N + n] : 0.0f);
}

// pad+convert inputs: [B][T][Din] float -> [B][T*Dpad] half
__global__ void conv_in(const float* __restrict__ src, __half* __restrict__ dst,
                        int Din, int Dpad)
{
    int idx = blockIdx.x * blockDim.x + threadIdx.x;
    int tot = BB * TT * Dpad;
    if (idx >= tot) return;
    int row = idx / (TT * Dpad);
    int rem = idx - row * (TT * Dpad);
    int t = rem / Dpad, k = rem - t * Dpad;
    float v = (k < Din) ? src[((size_t)row * TT + t) * Din + k] : 0.0f;
    dst[idx] = __float2half(v);
}

// ---------------- fp16 mma.sync GEMM, cp.async 3-stage, fused epilogues -----
// D = A[M,Kpad] @ Bt[N,Kpad]^T; A = concat(A1[:,0:K1], A2[:,0:HS], 0-pad)
// act: 0 bias->float C, 1 bias+relu->half C, 2 bias+tanh->half C, 3 LSTM cell
__global__ __launch_bounds__(256)
void mm_gemm(const __half* __restrict__ A1, int lda1, int K1,
             const __half* __restrict__ A2,
             const __half* __restrict__ Bt, int ldb,
             const float* __restrict__ bias,
             void* __restrict__ Cv, int ldc,
             int N, int Kpad, int act,
             float* __restrict__ c_state, __half* __restrict__ h_out,
             __half* __restrict__ seq_out, int t, int first)
{
    extern __shared__ __half smem[];
    const uint32_t sbase = smem_u32(smem);
    const int tid = threadIdx.x;
    const int wid = tid >> 5, lane = tid & 31;
    const int g = lane >> 2, tg = lane & 3;
    const int wM = (wid & 1) * 64, wN = (wid >> 1) * 32;
    const int rowBase = blockIdx.y * 128, colBase = blockIdx.x * 128;
    const int nT = Kpad >> 6;

    // async-copy coords: half-row (64B = 32 halfs) per thread per tile
    const int arow = tid >> 1;
    const int hseg = tid & 1;
    const int grow = rowBase + arow;
    const int gn = colBase + arow;
    const __half* bRow = Bt + (size_t)gn * ldb;
    const int bsz = (gn < N) ? 16 : 0;
    const uint32_t dstA = sbase + (uint32_t)(arow * 144 + hseg * 64);
    const uint32_t dstB = dstA + 18432u;

    auto issue = [&](int kt, int slot) {
        const int k0 = kt * 64 + hseg * 32;
        const uint32_t so = (uint32_t)slot * STG_BYTES;
#pragma unroll
        for (int j = 0; j < 4; j++) {
            int kg = k0 + j * 8;                   // halfs
            const void* p = A1;
            int sz = 0;
            if (kg < K1) { p = A1 + (size_t)grow * lda1 + kg; sz = 16; }
            else if (A2 != nullptr && kg < K1 + HS) {
                p = A2 + (size_t)grow * HS + (kg - K1); sz = 16;
            }
            cpa16(dstA + so + j * 16, p, sz);
        }
#pragma unroll
        for (int j = 0; j < 4; j++)
            cpa16(dstB + so + j * 16, bRow + k0 + j * 8, bsz);
        CPA_COMMIT();
    };

    float acc[4][4][4];
#pragma unroll
    for (int i = 0; i < 4; i++)
#pragma unroll
        for (int j = 0; j < 4; j++)
#pragma unroll
            for (int r = 0; r < 4; r++) acc[i][j][r] = 0.0f;

    issue(0, 0);
    if (nT > 1) issue(1, 1); else CPA_COMMIT();

    for (int kt = 0; kt < nT; kt++) {
        CPA_WAIT1();
        __syncthreads();
        if (kt + 2 < nT) issue(kt + 2, (kt + 2) % 3);

        const __half* As = smem + (kt % 3) * STG_HALFS;
        const __half* Bs = As + 9216;              // 128 rows * 72 halfs
#pragma unroll
        for (int ks = 0; ks < 4; ks++) {
            const int kb = ks * 16 + tg * 2;
            uint32_t af[4][4];
#pragma unroll
            for (int mt = 0; mt < 4; mt++) {
                const __half* pa = As + (wM + mt * 16 + g) * 72 + kb;
                af[mt][0] = *(const uint32_t*)(pa);
                af[mt][1] = *(const uint32_t*)(pa + 8 * 72);
                af[mt][2] = *(const uint32_t*)(pa + 8);
                af[mt][3] = *(const uint32_t*)(pa + 8 * 72 + 8);
            }
            uint32_t bf[4][2];
#pragma unroll
            for (int nt = 0; nt < 4; nt++) {
                const __half* pb = Bs + (wN + nt * 8 + g) * 72 + kb;
                bf[nt][0] = *(const uint32_t*)(pb);
                bf[nt][1] = *(const uint32_t*)(pb + 8);
            }
#pragma unroll
            for (int mt = 0; mt < 4; mt++)
#pragma unroll
                for (int nt = 0; nt < 4; nt++)
                    mma_f16(acc[mt][nt], af[mt], bf[nt]);
        }
    }
    __syncthreads();

    // ---- epilogues ----
    if (act == 3) {
        // cols are gate quads (i,f,g,o), u = col/4. Even-tg lane owns a quad:
        // it holds (i,f); odd partner lane holds (g,o) -> gather via shfl.
#pragma unroll
        for (int mt = 0; mt < 4; mt++) {
#pragma unroll
            for (int nt = 0; nt < 4; nt++) {
                float c0 = acc[mt][nt][0], c1 = acc[mt][nt][1];
                float c2 = acc[mt][nt][2], c3 = acc[mt][nt][3];
                float d0 = __shfl_xor_sync(0xFFFFFFFFu, c0, 1);
                float d1 = __shfl_xor_sync(0xFFFFFFFFu, c1, 1);
                float d2 = __shfl_xor_sync(0xFFFFFFFFu, c2, 1);
                float d3 = __shfl_xor_sync(0xFFFFFFFFu, c3, 1);
                if ((tg & 1) == 0) {
                    int quad = colBase + wN + nt * 8 + tg * 2;
                    if (quad < N) {
                        int u = quad >> 2;
                        float b0 = bias[quad], b1 = bias[quad + 1];
                        float b2 = bias[quad + 2], b3 = bias[quad + 3];
                        int row0 = rowBase + wM + mt * 16 + g;
#pragma unroll
                        for (int rr = 0; rr < 2; rr++) {
                            int row = row0 + rr * 8;
                            float zi = (rr ? c2 : c0) + b0;
                            float zf = (rr ? c3 : c1) + b1;
                            float zg = (rr ? d2 : d0) + b2;
                            float zo = (rr ? d3 : d1) + b3;
                            size_t ci = (size_t)row * UU + u;
                            float cp = first ? 0.0f : c_state[ci];
                            float cn = sigf(zf) * cp + sigf(zi) * tanhf(zg);
                            float hh = sigf(zo) * tanhf(cn);
                            c_state[ci] = cn;
                            __half hr = __float2half(hh);
                            h_out[(size_t)row * HS + u] = hr;
                            if (seq_out)
                                seq_out[(size_t)row * FDIMP + t * UU + u] = hr;
                        }
                    }
                }
            }
        }
    } else if (act == 0) {
        float* C = (float*)Cv;
#pragma unroll
        for (int mt = 0; mt < 4; mt++) {
#pragma unroll
            for (int nt = 0; nt < 4; nt++) {
                int col = colBase + wN + nt * 8 + tg * 2;
                if (col >= N) continue;
                float b0 = bias[col], b1 = bias[col + 1];
                int row0 = rowBase + wM + mt * 16 + g;
#pragma unroll
                for (int rr = 0; rr < 2; rr++) {
                    int row = row0 + rr * 8;
                    *(float2*)(C + (size_t)row * ldc + col) =
                        make_float2(acc[mt][nt][rr * 2] + b0,
                                    acc[mt][nt][rr * 2 + 1] + b1);
                }
            }
        }
    } else {
        __half* C = (__half*)Cv;
#pragma unroll
        for (int mt = 0; mt < 4; mt++) {
#pragma unroll
            for (int nt = 0; nt < 4; nt++) {
                int col = colBase + wN + nt * 8 + tg * 2;
                if (col >= N) continue;
                float b0 = bias[col], b1 = bias[col + 1];
                int row0 = rowBase + wM + mt * 16 + g;
#pragma unroll
                for (int rr = 0; rr < 2; rr++) {
                    int row = row0 + rr * 8;
                    float v0 = acc[mt][nt][rr * 2]     + b0;
                    float v1 = acc[mt][nt][rr * 2 + 1] + b1;
                    if (act == 1) { v0 = fmaxf(v0, 0.f); v1 = fmaxf(v1, 0.f); }
                    else          { v0 = tanhf(v0);      v1 = tanhf(v1); }
                    *(__half2*)(C + (size_t)row * ldc + col) =
                        __floats2half2_rn(v0, v1);
                }
            }
        }
    }
}

// ---------------- driver ----------------
extern "C" void kernel_launch(void* const* d_in, const int* in_sizes, int n_in,
                              void* d_out, int out_size)
{
    const float* x_batch = (const float*)d_in[0];
    const float* m_batch = (const float*)d_in[1];
    const float* enc_k   = (const float*)d_in[2];
    const float* enc_r   = (const float*)d_in[3];
    const float* enc_b   = (const float*)d_in[4];
    const float* dec_k   = (const float*)d_in[5];
    const float* dec_r   = (const float*)d_in[6];
    const float* dec_b   = (const float*)d_in[7];
    const float* W_map   = (const float*)d_in[8];
    const float* b_map   = (const float*)d_in[9];
    const float* W_d1    = (const float*)d_in[10];
    const float* b_d1    = (const float*)d_in[11];
    const float* W_d2    = (const float*)d_in[12];
    const float* b_d2    = (const float*)d_in[13];
    const float* W_out   = (const float*)d_in[14];
    const float* b_out   = (const float*)d_in[15];
    float* out = (float*)d_out;

    __half *wt_enc, *wt_dec, *wt_map, *wt_d1, *wt_d2, *wt_out;
    __half *xr, *mr, *h0, *h1, *dec, *mbuf, *dbuf;
    float *bi_enc, *bi_dec, *c;
    cudaGetSymbolAddress((void**)&wt_enc, g_wt_enc);
    cudaGetSymbolAddress((void**)&wt_dec, g_wt_dec);
    cudaGetSymbolAddress((void**)&bi_enc, g_bi_enc);
    cudaGetSymbolAddress((void**)&bi_dec, g_bi_dec);
    cudaGetSymbolAddress((void**)&wt_map, g_wt_map);
    cudaGetSymbolAddress((void**)&wt_d1,  g_wt_d1);
    cudaGetSymbolAddress((void**)&wt_d2,  g_wt_d2);
    cudaGetSymbolAddress((void**)&wt_out, g_wt_out);
    cudaGetSymbolAddress((void**)&xr,     g_xr);
    cudaGetSymbolAddress((void**)&mr,     g_mr);
    cudaGetSymbolAddress((void**)&h0,     g_h0);
    cudaGetSymbolAddress((void**)&h1,     g_h1);
    cudaGetSymbolAddress((void**)&c,      g_c);
    cudaGetSymbolAddress((void**)&dec,    g_dec);
    cudaGetSymbolAddress((void**)&mbuf,   g_m);
    cudaGetSymbolAddress((void**)&dbuf,   g_d);

    cudaFuncSetAttribute(mm_gemm, cudaFuncAttributeMaxDynamicSharedMemorySize, SMEM_BYTES);

    // ---- prep ----
    {
        int n1 = G4 * KP_LSTM;
        prep_lstm_w<<<(n1 + 255) / 256, 256>>>(enc_k, enc_r, enc_b, wt_enc, bi_enc,
                                               ENC_IN, KE1);
        prep_lstm_w<<<(n1 + 255) / 256, 256>>>(dec_k, dec_r, dec_b, wt_dec, bi_dec,
                                               DEC_IN, KD1);
        int n2 = HID * FDIMP;
        prep_trans<<<(n2 + 255) / 256, 256>>>(W_map, wt_map, FDIM, HID, FDIMP);
        int n3 = HID * HID;
        prep_trans<<<(n3 + 255) / 256, 256>>>(W_d1, wt_d1, HID, HID, HID);
        prep_trans<<<(n3 + 255) / 256, 256>>>(W_d2, wt_d2, HID, HID, HID);
        int n4 = ODIM * HID;
        prep_trans<<<(n4 + 255) / 256, 256>>>(W_out, wt_out, HID, ODIM, HID);
        int nx = BB * TT * KE1;
        conv_in<<<(nx + 255) / 256, 256>>>(x_batch, xr, ENC_IN, KE1);
        int nm = BB * TT * KD1;
        conv_in<<<(nm + 255) / 256, 256>>>(m_batch, mr, DEC_IN, KD1);
    }

    const dim3 gridLSTM((G4 + 127) / 128, BB / 128);   // 12 x 256
    const dim3 gridHID(HID / 128, BB / 128);           // 6 x 256
    const dim3 gridOUT((ODIM + 127) / 128, BB / 128);  // 2 x 256

    __half* hin = h0;
    __half* hout = h1;

    // ---- encoder ----
    // t=0: h=c=0 -> only x slice, Kpad = 64 (1 tile)
    mm_gemm<<<gridLSTM, 256, SMEM_BYTES>>>(
        xr, TT * KE1, KE1, nullptr, wt_enc, KP_LSTM, bi_enc,
        nullptr, 0, G4, 64, 3, c, hout, nullptr, 0, 1);
    { __half* tmp = hin; hin = hout; hout = tmp; }
    for (int t = 1; t < TT; t++) {
        mm_gemm<<<gridLSTM, 256, SMEM_BYTES>>>(
            xr + (size_t)t * KE1, TT * KE1, KE1, hin, wt_enc, KP_LSTM,
            bi_enc, nullptr, 0, G4, KP_LSTM, 3, c, hout, nullptr, t, 0);
        __half* tmp = hin; hin = hout; hout = tmp;
    }

    // ---- decoder ----
    for (int t = 0; t < TT; t++) {
        mm_gemm<<<gridLSTM, 256, SMEM_BYTES>>>(
            mr + (size_t)t * KD1, TT * KD1, KD1, hin, wt_dec, KP_LSTM,
            bi_dec, nullptr, 0, G4, KP_LSTM, 3, c, hout, dec, t, 0);
        __half* tmp = hin; hin = hout; hout = tmp;
    }

    // ---- MLP head ----
    mm_gemm<<<gridHID, 256, SMEM_BYTES>>>(
        dec, FDIMP, FDIMP, nullptr, wt_map, FDIMP, b_map,
        mbuf, HID, HID, FDIMP, 1, nullptr, nullptr, nullptr, 0, 0);
    mm_gemm<<<gridHID, 256, SMEM_BYTES>>>(
        mbuf, HID, HID, nullptr, wt_d1, HID, b_d1,
        dbuf, HID, HID, HID, 2, nullptr, nullptr, nullptr, 0, 0);
    mm_gemm<<<gridHID, 256, SMEM_BYTES>>>(
        dbuf, HID, HID, nullptr, wt_d2, HID, b_d2,
        mbuf, HID, HID, HID, 2, nullptr, nullptr, nullptr, 0, 0);
    mm_gemm<<<gridOUT, 256, SMEM_BYTES>>>(
        mbuf, HID, HID, nullptr, wt_out, HID, b_out,
        out, ODIM, ODIM, HID, 0, nullptr, nullptr, nullptr, 0, 0);
}

// round 7
// speedup vs baseline: 3.8005x; 1.0030x over previous
#include <cuda_runtime.h>
#include <cuda_fp16.h>
#include <math.h>
#include <stdint.h>

// ---------------- problem constants ----------------
#define BB 32768
#define TT 7
#define ENC_IN 60
#define DEC_IN 36
#define UU 356
#define G4 1424        // 4*UU
#define FDIM 2492      // TT*UU
#define FDIMP 2496     // padded (16B-aligned half rows)
#define HID 768
#define ODIM 168
#define HS 360         // padded h stride (halfs, 720B rows)
#define KE1 64         // enc x slice padded (60->64)
#define KD1 40         // dec m slice padded (36->40)
#define KP_LSTM 448    // 64+360=424 -> 448 (7 k-tiles of 64)

// smem: 3 stages x (A 128 rows x 144B + B 128 x 144B)
#define STG_BYTES  36864
#define STG_HALFS  (STG_BYTES / 2)
#define SMEM_BYTES (3 * STG_BYTES)         // 110592

// ---------------- scratch (device globals) ----------------
__device__ __half g_wt_enc[(size_t)G4 * KP_LSTM];   // [n=4u+gate][k]
__device__ __half g_wt_dec[(size_t)G4 * KP_LSTM];
__device__ float  g_bi_enc[G4];
__device__ float  g_bi_dec[G4];
__device__ __half g_wt_map[(size_t)HID * FDIMP];
__device__ __half g_wt_d1[(size_t)HID * HID];
__device__ __half g_wt_d2[(size_t)HID * HID];
__device__ __half g_wt_out[(size_t)ODIM * HID];
__device__ __half g_xr[(size_t)BB * TT * KE1];      // [B][T*64]
__device__ __half g_mr[(size_t)BB * TT * KD1];      // [B][T*40]
__device__ __half g_h0[(size_t)BB * HS];
__device__ __half g_h1[(size_t)BB * HS];
__device__ float  g_c[(size_t)BB * UU];
__device__ __half g_dec[(size_t)BB * FDIMP];
__device__ __half g_m[(size_t)BB * HID];
__device__ __half g_d[(size_t)BB * HID];

// ---------------- helpers ----------------
__device__ __forceinline__ uint32_t smem_u32(const void* p) {
    uint32_t a;
    asm("{ .reg .u64 t; cvta.to.shared.u64 t, %1; cvt.u32.u64 %0, t; }" : "=r"(a) : "l"(p));
    return a;
}
__device__ __forceinline__ void mma_f16(float* c, const uint32_t* a, const uint32_t* b) {
    asm volatile(
        "mma.sync.aligned.m16n8k16.row.col.f32.f16.f16.f32 "
        "{%0,%1,%2,%3}, {%4,%5,%6,%7}, {%8,%9}, {%0,%1,%2,%3};"
        : "+f"(c[0]), "+f"(c[1]), "+f"(c[2]), "+f"(c[3])
        : "r"(a[0]), "r"(a[1]), "r"(a[2]), "r"(a[3]), "r"(b[0]), "r"(b[1]));
}
__device__ __forceinline__ void ldm_x4(uint32_t* r, uint32_t addr) {
    asm volatile("ldmatrix.sync.aligned.m8n8.x4.shared.b16 {%0,%1,%2,%3}, [%4];"
                 : "=r"(r[0]), "=r"(r[1]), "=r"(r[2]), "=r"(r[3]) : "r"(addr));
}
__device__ __forceinline__ void cpa16(uint32_t dst, const void* src, int sz) {
    asm volatile("cp.async.cg.shared.global [%0], [%1], 16, %2;"
                 :: "r"(dst), "l"(src), "r"(sz) : "memory");
}
#define CPA_COMMIT() asm volatile("cp.async.commit_group;" ::: "memory")
#define CPA_WAIT1()  asm volatile("cp.async.wait_group 1;" ::: "memory")

__device__ __forceinline__ float sigf(float x) { return 1.0f / (1.0f + __expf(-x)); }

// ---------------- prep kernels (once per launch; ~tens of us) ---------------
__global__ void prep_lstm_w(const float* __restrict__ Kx, const float* __restrict__ R,
                            const float* __restrict__ b, __half* __restrict__ Wt,
                            float* __restrict__ biasI, int KX, int K1)
{
    int idx = blockIdx.x * blockDim.x + threadIdx.x;
    if (idx >= G4 * KP_LSTM) return;
    int n = idx / KP_LSTM, k = idx - n * KP_LSTM;
    int u = n >> 2, gate = n & 3;
    int colw = gate * UU + u;
    float v = 0.0f;
    if (k < KX) v = Kx[(size_t)k * G4 + colw];
    else if (k >= K1 && k < K1 + UU) v = R[(size_t)(k - K1) * G4 + colw];
    Wt[idx] = __float2half(v);
    if (k == 0) biasI[n] = b[colw];
}

__global__ void prep_trans(const float* __restrict__ W, __half* __restrict__ Wt,
                           int K, int N, int Kpad)
{
    int idx = blockIdx.x * blockDim.x + threadIdx.x;
    if (idx >= N * Kpad) return;
    int n = idx / Kpad, k = idx - n * Kpad;
    Wt[idx] = __float2half((k < K) ? W[(size_t)k * N + n] : 0.0f);
}

__global__ void conv_in(const float* __restrict__ src, __half* __restrict__ dst,
                        int Din, int Dpad)
{
    int idx = blockIdx.x * blockDim.x + threadIdx.x;
    int tot = BB * TT * Dpad;
    if (idx >= tot) return;
    int row = idx / (TT * Dpad);
    int rem = idx - row * (TT * Dpad);
    int t = rem / Dpad, k = rem - t * Dpad;
    float v = (k < Din) ? src[((size_t)row * TT + t) * Din + k] : 0.0f;
    dst[idx] = __float2half(v);
}

// ---------------- fp16 mma GEMM: cp.async 3-stage + ldmatrix fragments ------
// D = A[M,Kpad] @ Bt[N,Kpad]^T; A = concat(A1[:,0:K1], A2[:,0:HS], 0-pad)
// act: 0 bias->float C, 1 bias+relu->half C, 2 bias+tanh->half C, 3 LSTM cell
__global__ __launch_bounds__(256)
void mm_gemm(const __half* __restrict__ A1, int lda1, int K1,
             const __half* __restrict__ A2,
             const __half* __restrict__ Bt, int ldb,
             const float* __restrict__ bias,
             void* __restrict__ Cv, int ldc,
             int N, int Kpad, int act,
             float* __restrict__ c_state, __half* __restrict__ h_out,
             __half* __restrict__ seq_out, int t, int first)
{
    extern __shared__ __half smem[];
    const uint32_t sbase = smem_u32(smem);
    const int tid = threadIdx.x;
    const int wid = tid >> 5, lane = tid & 31;
    const int g = lane >> 2, tg = lane & 3;
    const int wM = (wid & 1) * 64, wN = (wid >> 1) * 32;
    const int rowBase = blockIdx.y * 128, colBase = blockIdx.x * 128;
    const int nT = Kpad >> 6;

    // cp.async coords: half-row (64B = 32 halfs) per thread per tile
    const int arow = tid >> 1;
    const int hseg = tid & 1;
    const int grow = rowBase + arow;
    const int gn = colBase + arow;
    const __half* bRow = Bt + (size_t)gn * ldb;
    const int bsz = (gn < N) ? 16 : 0;
    const uint32_t dstA = sbase + (uint32_t)(arow * 144 + hseg * 64);
    const uint32_t dstB = dstA + 18432u;

    // ldmatrix per-lane offsets (bytes)
    const int lm = lane >> 3, lr = lane & 7;
    const uint32_t aoff = (uint32_t)((((lm & 1) << 3) + lr) * 144 + ((lm >> 1) << 4));
    const uint32_t boff = (uint32_t)(((lm >> 1) * 8 + lr) * 144 + ((lm & 1) << 4));
    const uint32_t aBaseW = sbase + (uint32_t)(wM * 144) + aoff;
    const uint32_t bBaseW = sbase + 18432u + (uint32_t)(wN * 144) + boff;

    auto issue = [&](int kt, int slot) {
        const int k0 = kt * 64 + hseg * 32;
        const uint32_t so = (uint32_t)slot * STG_BYTES;
#pragma unroll
        for (int j = 0; j < 4; j++) {
            int kg = k0 + j * 8;
            const void* p = A1;
            int sz = 0;
            if (kg < K1) { p = A1 + (size_t)grow * lda1 + kg; sz = 16; }
            else if (A2 != nullptr && kg < K1 + HS) {
                p = A2 + (size_t)grow * HS + (kg - K1); sz = 16;
            }
            cpa16(dstA + so + j * 16, p, sz);
        }
#pragma unroll
        for (int j = 0; j < 4; j++)
            cpa16(dstB + so + j * 16, bRow + k0 + j * 8, bsz);
        CPA_COMMIT();
    };

    float acc[4][4][4];
#pragma unroll
    for (int i = 0; i < 4; i++)
#pragma unroll
        for (int j = 0; j < 4; j++)
#pragma unroll
            for (int r = 0; r < 4; r++) acc[i][j][r] = 0.0f;

    issue(0, 0);
    if (nT > 1) issue(1, 1); else CPA_COMMIT();

    for (int kt = 0; kt < nT; kt++) {
        CPA_WAIT1();
        __syncthreads();
        if (kt + 2 < nT) issue(kt + 2, (kt + 2) % 3);

        const uint32_t so = (uint32_t)((kt % 3) * STG_BYTES);
#pragma unroll
        for (int ks = 0; ks < 4; ks++) {
            const uint32_t kb = so + (uint32_t)(ks * 32);   // bytes
            uint32_t af[4][4];
#pragma unroll
            for (int mt = 0; mt < 4; mt++)
                ldm_x4(af[mt], aBaseW + kb + (uint32_t)(mt * 16 * 144));
            uint32_t bf[4][2];
#pragma unroll
            for (int np = 0; np < 2; np++) {
                uint32_t r4[4];
                ldm_x4(r4, bBaseW + kb + (uint32_t)(np * 16 * 144));
                bf[np * 2][0] = r4[0]; bf[np * 2][1] = r4[1];
                bf[np * 2 + 1][0] = r4[2]; bf[np * 2 + 1][1] = r4[3];
            }
#pragma unroll
            for (int mt = 0; mt < 4; mt++)
#pragma unroll
                for (int nt = 0; nt < 4; nt++)
                    mma_f16(acc[mt][nt], af[mt], bf[nt]);
        }
    }

    // ---- epilogues (register-only; no smem) ----
    if (act == 3) {
        // cols are gate quads (i,f,g,o), u = col/4. Even-tg lane owns a quad:
        // it holds (i,f); odd partner lane holds (g,o) -> gather via shfl.
#pragma unroll
        for (int mt = 0; mt < 4; mt++) {
#pragma unroll
            for (int nt = 0; nt < 4; nt++) {
                float c0 = acc[mt][nt][0], c1 = acc[mt][nt][1];
                float c2 = acc[mt][nt][2], c3 = acc[mt][nt][3];
                float d0 = __shfl_xor_sync(0xFFFFFFFFu, c0, 1);
                float d1 = __shfl_xor_sync(0xFFFFFFFFu, c1, 1);
                float d2 = __shfl_xor_sync(0xFFFFFFFFu, c2, 1);
                float d3 = __shfl_xor_sync(0xFFFFFFFFu, c3, 1);
                if ((tg & 1) == 0) {
                    int quad = colBase + wN + nt * 8 + tg * 2;
                    if (quad < N) {
                        int u = quad >> 2;
                        float b0 = bias[quad], b1 = bias[quad + 1];
                        float b2 = bias[quad + 2], b3 = bias[quad + 3];
                        int row0 = rowBase + wM + mt * 16 + g;
#pragma unroll
                        for (int rr = 0; rr < 2; rr++) {
                            int row = row0 + rr * 8;
                            float zi = (rr ? c2 : c0) + b0;
                            float zf = (rr ? c3 : c1) + b1;
                            float zg = (rr ? d2 : d0) + b2;
                            float zo = (rr ? d3 : d1) + b3;
                            size_t ci = (size_t)row * UU + u;
                            float cp = first ? 0.0f : c_state[ci];
                            float cn = sigf(zf) * cp + sigf(zi) * tanhf(zg);
                            float hh = sigf(zo) * tanhf(cn);
                            c_state[ci] = cn;
                            __half hr = __float2half(hh);
                            h_out[(size_t)row * HS + u] = hr;
                            if (seq_out)
                                seq_out[(size_t)row * FDIMP + t * UU + u] = hr;
                        }
                    }
                }
            }
        }
    } else if (act == 0) {
        float* C = (float*)Cv;
#pragma unroll
        for (int mt = 0; mt < 4; mt++) {
#pragma unroll
            for (int nt = 0; nt < 4; nt++) {
                int col = colBase + wN + nt * 8 + tg * 2;
                if (col >= N) continue;
                float b0 = bias[col], b1 = bias[col + 1];
                int row0 = rowBase + wM + mt * 16 + g;
#pragma unroll
                for (int rr = 0; rr < 2; rr++) {
                    int row = row0 + rr * 8;
                    *(float2*)(C + (size_t)row * ldc + col) =
                        make_float2(acc[mt][nt][rr * 2] + b0,
                                    acc[mt][nt][rr * 2 + 1] + b1);
                }
            }
        }
    } else {
        __half* C = (__half*)Cv;
#pragma unroll
        for (int mt = 0; mt < 4; mt++) {
#pragma unroll
            for (int nt = 0; nt < 4; nt++) {
                int col = colBase + wN + nt * 8 + tg * 2;
                if (col >= N) continue;
                float b0 = bias[col], b1 = bias[col + 1];
                int row0 = rowBase + wM + mt * 16 + g;
#pragma unroll
                for (int rr = 0; rr < 2; rr++) {
                    int row = row0 + rr * 8;
                    float v0 = acc[mt][nt][rr * 2]     + b0;
                    float v1 = acc[mt][nt][rr * 2 + 1] + b1;
                    if (act == 1) { v0 = fmaxf(v0, 0.f); v1 = fmaxf(v1, 0.f); }
                    else          { v0 = tanhf(v0);      v1 = tanhf(v1); }
                    *(__half2*)(C + (size_t)row * ldc + col) =
                        __floats2half2_rn(v0, v1);
                }
            }
        }
    }
}

// ---------------- driver ----------------
extern "C" void kernel_launch(void* const* d_in, const int* in_sizes, int n_in,
                              void* d_out, int out_size)
{
    const float* x_batch = (const float*)d_in[0];
    const float* m_batch = (const float*)d_in[1];
    const float* enc_k   = (const float*)d_in[2];
    const float* enc_r   = (const float*)d_in[3];
    const float* enc_b   = (const float*)d_in[4];
    const float* dec_k   = (const float*)d_in[5];
    const float* dec_r   = (const float*)d_in[6];
    const float* dec_b   = (const float*)d_in[7];
    const float* W_map   = (const float*)d_in[8];
    const float* b_map   = (const float*)d_in[9];
    const float* W_d1    = (const float*)d_in[10];
    const float* b_d1    = (const float*)d_in[11];
    const float* W_d2    = (const float*)d_in[12];
    const float* b_d2    = (const float*)d_in[13];
    const float* W_out   = (const float*)d_in[14];
    const float* b_out   = (const float*)d_in[15];
    float* out = (float*)d_out;

    __half *wt_enc, *wt_dec, *wt_map, *wt_d1, *wt_d2, *wt_out;
    __half *xr, *mr, *h0, *h1, *dec, *mbuf, *dbuf;
    float *bi_enc, *bi_dec, *c;
    cudaGetSymbolAddress((void**)&wt_enc, g_wt_enc);
    cudaGetSymbolAddress((void**)&wt_dec, g_wt_dec);
    cudaGetSymbolAddress((void**)&bi_enc, g_bi_enc);
    cudaGetSymbolAddress((void**)&bi_dec, g_bi_dec);
    cudaGetSymbolAddress((void**)&wt_map, g_wt_map);
    cudaGetSymbolAddress((void**)&wt_d1,  g_wt_d1);
    cudaGetSymbolAddress((void**)&wt_d2,  g_wt_d2);
    cudaGetSymbolAddress((void**)&wt_out, g_wt_out);
    cudaGetSymbolAddress((void**)&xr,     g_xr);
    cudaGetSymbolAddress((void**)&mr,     g_mr);
    cudaGetSymbolAddress((void**)&h0,     g_h0);
    cudaGetSymbolAddress((void**)&h1,     g_h1);
    cudaGetSymbolAddress((void**)&c,      g_c);
    cudaGetSymbolAddress((void**)&dec,    g_dec);
    cudaGetSymbolAddress((void**)&mbuf,   g_m);
    cudaGetSymbolAddress((void**)&dbuf,   g_d);

    cudaFuncSetAttribute(mm_gemm, cudaFuncAttributeMaxDynamicSharedMemorySize, SMEM_BYTES);

    // ---- prep ----
    {
        int n1 = G4 * KP_LSTM;
        prep_lstm_w<<<(n1 + 255) / 256, 256>>>(enc_k, enc_r, enc_b, wt_enc, bi_enc,
                                               ENC_IN, KE1);
        prep_lstm_w<<<(n1 + 255) / 256, 256>>>(dec_k, dec_r, dec_b, wt_dec, bi_dec,
                                               DEC_IN, KD1);
        int n2 = HID * FDIMP;
        prep_trans<<<(n2 + 255) / 256, 256>>>(W_map, wt_map, FDIM, HID, FDIMP);
        int n3 = HID * HID;
        prep_trans<<<(n3 + 255) / 256, 256>>>(W_d1, wt_d1, HID, HID, HID);
        prep_trans<<<(n3 + 255) / 256, 256>>>(W_d2, wt_d2, HID, HID, HID);
        int n4 = ODIM * HID;
        prep_trans<<<(n4 + 255) / 256, 256>>>(W_out, wt_out, HID, ODIM, HID);
        int nx = BB * TT * KE1;
        conv_in<<<(nx + 255) / 256, 256>>>(x_batch, xr, ENC_IN, KE1);
        int nm = BB * TT * KD1;
        conv_in<<<(nm + 255) / 256, 256>>>(m_batch, mr, DEC_IN, KD1);
    }

    const dim3 gridLSTM((G4 + 127) / 128, BB / 128);   // 12 x 256
    const dim3 gridHID(HID / 128, BB / 128);           // 6 x 256
    const dim3 gridOUT((ODIM + 127) / 128, BB / 128);  // 2 x 256

    __half* hin = h0;
    __half* hout = h1;

    // ---- encoder ----
    mm_gemm<<<gridLSTM, 256, SMEM_BYTES>>>(
        xr, TT * KE1, KE1, nullptr, wt_enc, KP_LSTM, bi_enc,
        nullptr, 0, G4, 64, 3, c, hout, nullptr, 0, 1);
    { __half* tmp = hin; hin = hout; hout = tmp; }
    for (int t = 1; t < TT; t++) {
        mm_gemm<<<gridLSTM, 256, SMEM_BYTES>>>(
            xr + (size_t)t * KE1, TT * KE1, KE1, hin, wt_enc, KP_LSTM,
            bi_enc, nullptr, 0, G4, KP_LSTM, 3, c, hout, nullptr, t, 0);
        __half* tmp = hin; hin = hout; hout = tmp;
    }

    // ---- decoder ----
    for (int t = 0; t < TT; t++) {
        mm_gemm<<<gridLSTM, 256, SMEM_BYTES>>>(
            mr + (size_t)t * KD1, TT * KD1, KD1, hin, wt_dec, KP_LSTM,
            bi_dec, nullptr, 0, G4, KP_LSTM, 3, c, hout, dec, t, 0);
        __half* tmp = hin; hin = hout; hout = tmp;
    }

    // ---- MLP head ----
    mm_gemm<<<gridHID, 256, SMEM_BYTES>>>(
        dec, FDIMP, FDIMP, nullptr, wt_map, FDIMP, b_map,
        mbuf, HID, HID, FDIMP, 1, nullptr, nullptr, nullptr, 0, 0);
    mm_gemm<<<gridHID, 256, SMEM_BYTES>>>(
        mbuf, HID, HID, nullptr, wt_d1, HID, b_d1,
        dbuf, HID, HID, HID, 2, nullptr, nullptr, nullptr, 0, 0);
    mm_gemm<<<gridHID, 256, SMEM_BYTES>>>(
        dbuf, HID, HID, nullptr, wt_d2, HID, b_d2,
        mbuf, HID, HID, HID, 2, nullptr, nullptr, nullptr, 0, 0);
    mm_gemm<<<gridOUT, 256, SMEM_BYTES>>>(
        mbuf, HID, HID, nullptr, wt_out, HID, b_out,
        out, ODIM, ODIM, HID, 0, nullptr, nullptr, nullptr, 0, 0);
}